// round 2
// baseline (speedup 1.0000x reference)
#include <cuda_runtime.h>
#include <cuda_bf16.h>

#define MAXN 50000
#define MAXE 800000

// Scratch (allocation-free: __device__ globals)
__device__ __align__(16) float g_xagg[MAXN * 2];    // A @ x           [N,2]
__device__ __align__(16) float g_t2[MAXN * 64];     // h1 @ W2         [N,64]
__device__ __align__(16) float g_h2agg[MAXN * 64];  // A @ t2          [N,64]
__device__ __align__(16) float g_t3[MAXN];          // h2 @ W3         [N,1]

// K0: zero accumulators, init out = b3
__global__ void init_kernel(const float* __restrict__ b3, float* __restrict__ out, int n) {
    int i = blockIdx.x * blockDim.x + threadIdx.x;
    if (i < n * 64) g_h2agg[i] = 0.f;
    if (i < n * 2)  g_xagg[i]  = 0.f;
    if (i < n)      out[i]     = b3[0];
}

// K1: layer-1 aggregation moved BEFORE the GEMM: xagg[dst] += w * x[src]  (2 floats/edge)
__global__ void scatter1_kernel(const float* __restrict__ x,
                                const int* __restrict__ ei,
                                const float* __restrict__ ew, int e) {
    int idx = blockIdx.x * blockDim.x + threadIdx.x;
    if (idx >= e) return;
    int s = ei[idx];
    int d = ei[e + idx];
    float w = ew[idx];
    float2 xv = *(const float2*)(x + (long long)s * 2);
    float* p = g_xagg + (long long)d * 2;
    asm volatile("red.global.add.v2.f32 [%0], {%1,%2};"
                 :: "l"(p), "f"(w * xv.x), "f"(w * xv.y) : "memory");
}

// K2: fused dense: h1 = relu(xagg@W1 + b1) (in smem), then t2 = h1@W2.
// One block (128 thr) per node; phase 2 splits the K=128 reduction across two
// 64-thread halves so all 128 threads stay busy.
__global__ void dense12_kernel(const float* __restrict__ W1,
                               const float* __restrict__ b1,
                               const float* __restrict__ W2, int n) {
    int i = blockIdx.x;
    if (i >= n) return;
    int tid = threadIdx.x;  // 0..127
    __shared__ float sh[128];
    __shared__ float sp[64];
    float x0 = g_xagg[i * 2 + 0];
    float x1 = g_xagg[i * 2 + 1];
    float h = fmaf(x0, W1[tid], fmaf(x1, W1[128 + tid], b1[tid]));
    sh[tid] = fmaxf(h, 0.f);
    __syncthreads();
    int j  = tid & 63;
    int k0 = (tid >> 6) * 64;
    float acc = 0.f;
#pragma unroll 16
    for (int k = 0; k < 64; k++)
        acc = fmaf(sh[k0 + k], W2[(k0 + k) * 64 + j], acc);
    if (tid >= 64) sp[j] = acc;
    __syncthreads();
    if (tid < 64) g_t2[i * 64 + j] = acc + sp[j];
}

// K3: layer-2 aggregation: h2agg[dst] += w * t2[src]  (64 floats/edge).
// 16 threads per edge, one red.global.add.v4.f32 each (4x fewer L2 atomics).
__global__ void scatter2_kernel(const int* __restrict__ ei,
                                const float* __restrict__ ew, int e) {
    int t = blockIdx.x * blockDim.x + threadIdx.x;
    if (t >= e * 16) return;
    int eidx = t >> 4;
    int c    = t & 15;
    int s = ei[eidx];
    int d = ei[e + eidx];
    float w = ew[eidx];
    float4 v = *(const float4*)(g_t2 + (long long)s * 64 + c * 4);
    float* p = g_h2agg + (long long)d * 64 + c * 4;
    asm volatile("red.global.add.v4.f32 [%0], {%1,%2,%3,%4};"
                 :: "l"(p), "f"(w * v.x), "f"(w * v.y), "f"(w * v.z), "f"(w * v.w)
                 : "memory");
}

// K4: t3 = relu(h2agg + b2) @ W3   (warp per node, shuffle reduce)
__global__ void dense3_kernel(const float* __restrict__ b2,
                              const float* __restrict__ W3, int n) {
    int gtid = blockIdx.x * blockDim.x + threadIdx.x;
    int node = gtid >> 5;
    int lane = gtid & 31;
    if (node >= n) return;
    const float* row = g_h2agg + (long long)node * 64;
    float a = fmaxf(row[lane] + b2[lane], 0.f) * W3[lane]
            + fmaxf(row[lane + 32] + b2[lane + 32], 0.f) * W3[lane + 32];
#pragma unroll
    for (int o = 16; o; o >>= 1) a += __shfl_xor_sync(0xffffffffu, a, o);
    if (lane == 0) g_t3[node] = a;
}

// K5: layer-3 aggregation straight into out (pre-initialized to b3): 1 float/edge
__global__ void scatter3_kernel(const int* __restrict__ ei,
                                const float* __restrict__ ew,
                                float* __restrict__ out, int e) {
    int idx = blockIdx.x * blockDim.x + threadIdx.x;
    if (idx >= e) return;
    int s = ei[idx];
    int d = ei[e + idx];
    atomicAdd(out + d, ew[idx] * g_t3[s]);
}

extern "C" void kernel_launch(void* const* d_in, const int* in_sizes, int n_in,
                              void* d_out, int out_size) {
    const float* x  = (const float*)d_in[0];
    const int*   ei = (const int*)d_in[1];
    const float* ew = (const float*)d_in[2];
    const float* W1 = (const float*)d_in[3];
    const float* b1 = (const float*)d_in[4];
    const float* W2 = (const float*)d_in[5];
    const float* b2 = (const float*)d_in[6];
    const float* W3 = (const float*)d_in[7];
    const float* b3 = (const float*)d_in[8];
    float* out = (float*)d_out;

    int n = in_sizes[0] / 2;   // 50000
    int e = in_sizes[2];       // 800000

    init_kernel<<<(n * 64 + 255) / 256, 256>>>(b3, out, n);
    scatter1_kernel<<<(e + 255) / 256, 256>>>(x, ei, ew, e);
    dense12_kernel<<<n, 128>>>(W1, b1, W2, n);
    long long total2 = (long long)e * 16;
    scatter2_kernel<<<(int)((total2 + 255) / 256), 256>>>(ei, ew, e);
    dense3_kernel<<<(n * 32 + 255) / 256, 256>>>(b2, W3, n);
    scatter3_kernel<<<(e + 255) / 256, 256>>>(ei, ew, out, e);
}